// round 9
// baseline (speedup 1.0000x reference)
#include <cuda_runtime.h>

// IF (integrate-and-fire) scan. x: (B=32, T=8, CHW=200704) fp32.
// HBM-roofline streaming kernel (~7.2TB/s effective bidirectional).
// R1-R8: kernel time is structure-invariant (56.96-58.4us) across caching
// hints, unroll depth, persistence, grid geometry, phase separation.
// R9 (final probe): write-through stores (__stwt) — output is never read,
// so skip L2 dirty-line allocation entirely; store path becomes a pure
// posted write stream with no tail writeback flush. Same 411MB traffic.

#define T_STEPS 8
#define BATCH 32
#define CHW4 50176              // (64*56*56)/4 float4 per timestep-slice
#define VTH 1.0f

__global__ void __launch_bounds__(256) if_scan_kernel(
    const float4* __restrict__ x, float4* __restrict__ out)
{
    const int p = blockIdx.x * 256 + threadIdx.x;     // 0 .. CHW4-1, exact
    const int b = blockIdx.y;                          // batch index
    const long long base = (long long)b * (T_STEPS * CHW4) + p;

    // Load burst: 8 independent LDG.128 (MLP=8)
    float4 xt[T_STEPS];
#pragma unroll
    for (int t = 0; t < T_STEPS; t++)
        xt[t] = x[base + t * CHW4];

    float mx = 0.f, my = 0.f, mz = 0.f, mw = 0.f;
#pragma unroll
    for (int t = 0; t < T_STEPS; t++) {
        mx += xt[t].x; my += xt[t].y; mz += xt[t].z; mw += xt[t].w;
        float4 s;
        s.x = (mx > VTH) ? 1.0f : 0.0f;
        s.y = (my > VTH) ? 1.0f : 0.0f;
        s.z = (mz > VTH) ? 1.0f : 0.0f;
        s.w = (mw > VTH) ? 1.0f : 0.0f;
        mx = (mx > VTH) ? 0.0f : mx;
        my = (my > VTH) ? 0.0f : my;
        mz = (mz > VTH) ? 0.0f : mz;
        mw = (mw > VTH) ? 0.0f : mw;
        // Write-through: never-read output, no L2 dirty-line allocation.
        __stwt(out + base + t * CHW4, s);
    }
}

extern "C" void kernel_launch(void* const* d_in, const int* in_sizes, int n_in,
                              void* d_out, int out_size)
{
    const float4* x = (const float4*)d_in[0];
    float4* out = (float4*)d_out;
    dim3 grid(CHW4 / 256, BATCH, 1);   // (196, 32)
    if_scan_kernel<<<grid, 256>>>(x, out);
}